// round 11
// baseline (speedup 1.0000x reference)
#include <cuda_runtime.h>
#include <math.h>

#define Bn 16
#define Sn 257
#define Hn 768
#define Vn 30522
#define Pn 32
#define Kn 8
#define NROWS (Bn * 256)
#define HALFV (Vn / 2)   // 15261 float2 per row
#define N4    7630       // float4 count in the aligned body of a row
#define CAP 512          // candidate buffer (expected ~41 used)

#define TILE4   512      // float4 per tile (8KB)
#define NTILES  15       // 14 full + 1 remainder (462 float4)
#define FULLT   14       // tiles 0..13 need no bounds checks
#define STAGES  4
#define ROWS_DSMEM (STAGES * TILE4 * 16)   // 32KB

// Output layout (flat f32, reference tuple order)
#define OFF_COND 0
#define OFF_MARG 1
#define OFF_RM   2
#define OFF_SS   (OFF_RM + Bn * Vn)
#define OFF_MASK (OFF_SS + Bn * Vn)
#define OFF_RR   (OFF_MASK + Bn * 256)
#define OFF_IDS  (OFF_RR + Bn * Vn)
#define OFF_ER   (OFF_IDS + NROWS * Kn)
#define OFF_W    (OFF_ER + NROWS * Pn)

__device__ float g_rowinv[NROWS];
__device__ float g_pos;

typedef unsigned long long u64;
typedef unsigned int u32;

__global__ void zero_kernel(float* __restrict__ out) {
    int i = blockIdx.x * blockDim.x + threadIdx.x;
    if (i < OFF_SS) out[i] = 0.f;
    if (i == 0) g_pos = 0.f;
}

// spacer (position 3) so rows_kernel lands in the ncu capture window (pos 4)
__global__ void spacer_kernel() {}

// ---- monotone (value,index) packing: larger value first, ties -> smaller idx ----
__device__ __forceinline__ u64 packvi(float f, int idx) {
    u32 u = __float_as_uint(f);
    u = (u & 0x80000000u) ? ~u : (u | 0x80000000u);
    return ((u64)u << 32) | (u32)(0xFFFFFFFFu - (u32)idx);
}
__device__ __forceinline__ float unpackv(u64 p) {
    u32 k = (u32)(p >> 32);
    u32 u = (k & 0x80000000u) ? (k & 0x7FFFFFFFu) : ~k;
    return __uint_as_float(u);
}
__device__ __forceinline__ int unpacki(u64 p) {
    return (int)(0xFFFFFFFFu - (u32)p);
}

// Warp-distributed sorted top-8 insert: lanes 0..7 hold the list (lane0 =
// largest). pk must be warp-uniform.
__device__ __forceinline__ void winsert(u64& ldist, u64 pk, int lane) {
    u64 up = __shfl_up_sync(0xffffffffu, ldist, 1);
    if (lane == 0) up = ~0ull;                       // +inf sentinel
    ldist = (ldist >= pk) ? ldist : ((up >= pk) ? pk : up);
}

__device__ __forceinline__ void cpa16(float4* dst_smem, const float4* src) {
    u32 d = (u32)__cvta_generic_to_shared(dst_smem);
    asm volatile("cp.async.cg.shared.global [%0], [%1], 16;" :: "r"(d), "l"(src));
}
__device__ __forceinline__ void cpa_commit() {
    asm volatile("cp.async.commit_group;");
}
__device__ __forceinline__ void cpa_wait3() {
    asm volatile("cp.async.wait_group 3;");
}

// ---------------- Kernel A: per-(b,s) row pass over V ----------------
// sumexp (no max subtraction: logits O(1), exp(lg)/sum == ref softmax) +
// threshold-gathered top-8 (fallback rescan keeps correctness for ANY input).
// cp.async 4-stage smem pipeline. Consume phase minimized: one threshold
// branch per 8 elements, no bounds checks in full tiles, incremental index.
__global__ __launch_bounds__(256, 6) void rows_kernel(const float* __restrict__ logits,
                                                      const float* __restrict__ attn,
                                                      float* __restrict__ out) {
    extern __shared__ float4 stage[];   // [STAGES * TILE4]
    const int row = blockIdx.x;
    const int b = row >> 8;
    const int s = row & 255;
    const int tid = threadIdx.x;
    const int lane = tid & 31;
    const int wid = tid >> 5;

    const size_t fbase = ((size_t)b * Sn + (s + 1)) * Vn;   // float index of row start
    const float* __restrict__ rowp = logits + fbase;
    const int off = (int)(fbase & 3);                        // 0 or 2
    const float4* __restrict__ lp4 = (const float4*)(rowp + off);
    const int e0 = (off == 2) ? 0 : (Vn - 2);                // the 2 peeled elements

    __shared__ int   cnt;
    __shared__ u64   cand[CAP];
    __shared__ float wsum[8];
    __shared__ u64   fin[Kn];
    __shared__ float bsum;
    if (tid == 0) cnt = 0;
    __syncthreads();

    const float T = 3.0f;
    float sum0 = 0.f, sum1 = 0.f, sum2 = 0.f, sum3 = 0.f;

#define PUSH(f, ix)                                                      \
    {                                                                    \
        int _p = atomicAdd(&cnt, 1);                                     \
        if (_p < CAP) cand[_p] = packvi((f), (ix));                      \
    }
// merged: 2 float4 (8 elements), ONE branch
#define PROC8(v0, v1, ix0, ix1)                                          \
    {                                                                    \
        sum0 += __expf((v0).x);  sum1 += __expf((v0).y);                 \
        sum2 += __expf((v0).z);  sum3 += __expf((v0).w);                 \
        sum0 += __expf((v1).x);  sum1 += __expf((v1).y);                 \
        sum2 += __expf((v1).z);  sum3 += __expf((v1).w);                 \
        float _m0 = fmaxf(fmaxf((v0).x, (v0).y), fmaxf((v0).z, (v0).w)); \
        float _m1 = fmaxf(fmaxf((v1).x, (v1).y), fmaxf((v1).z, (v1).w)); \
        if (fmaxf(_m0, _m1) >= T) {  /* rare */                          \
            if ((v0).x >= T) PUSH((v0).x, (ix0));                        \
            if ((v0).y >= T) PUSH((v0).y, (ix0) + 1);                    \
            if ((v0).z >= T) PUSH((v0).z, (ix0) + 2);                    \
            if ((v0).w >= T) PUSH((v0).w, (ix0) + 3);                    \
            if ((v1).x >= T) PUSH((v1).x, (ix1));                        \
            if ((v1).y >= T) PUSH((v1).y, (ix1) + 1);                    \
            if ((v1).z >= T) PUSH((v1).z, (ix1) + 2);                    \
            if ((v1).w >= T) PUSH((v1).w, (ix1) + 3);                    \
        }                                                                \
    }

    // peeled scalar elements (2 per row, handled by tid 0/1)
    if (tid < 2) {
        float f = rowp[e0 + tid];
        sum0 += __expf(f);
        if (f >= T) PUSH(f, e0 + tid);
    }

    // fetch tile t into slot t%STAGES (thread-private 16B cells); empty
    // commit for t >= NTILES keeps the wait_group count uniform.
#define FETCH(t)                                                              \
    {                                                                         \
        if ((t) < NTILES) {                                                   \
            int _base = (t) * TILE4;                                          \
            float4* _slot = stage + ((t) % STAGES) * TILE4;                   \
            _Pragma("unroll")                                                 \
            for (int _j = 0; _j < 2; _j++) {                                  \
                int _i = _j * 256 + tid;                                      \
                if (_base + _i < N4) cpa16(_slot + _i, lp4 + _base + _i);     \
            }                                                                 \
        }                                                                     \
        cpa_commit();                                                         \
    }

    FETCH(0); FETCH(1); FETCH(2); FETCH(3);
    int ix0 = off + 4 * tid;               // element index of slot[tid] in tile t
#pragma unroll 1
    for (int t = 0; t < FULLT; t++, ix0 += 4 * TILE4) {
        cpa_wait3();                       // tile t complete (4 pending -> 3)
        float4* slot = stage + (t % STAGES) * TILE4;
        float4 r0 = slot[tid];
        float4 r1 = slot[256 + tid];
        FETCH(t + 4);                      // refill this slot (own cells only)
        PROC8(r0, r1, ix0, ix0 + 1024);
    }
    // last tile (462 float4): guarded
    {
        cpa_wait3();
        const int base = FULLT * TILE4;
        float4* slot = stage + (FULLT % STAGES) * TILE4;
        const float4 NEG4 = make_float4(-INFINITY, -INFINITY, -INFINITY, -INFINITY);
        float4 r0 = (base + tid < N4)       ? slot[tid]       : NEG4;
        float4 r1 = (base + 256 + tid < N4) ? slot[256 + tid] : NEG4;
        asm volatile("cp.async.wait_group 0;");   // drain
        PROC8(r0, r1, ix0, ix0 + 1024);
    }

    // ---- softmax-sum reduce ----
    float sum = (sum0 + sum1) + (sum2 + sum3);
#pragma unroll
    for (int offs = 16; offs; offs >>= 1) sum += __shfl_xor_sync(0xffffffffu, sum, offs);
    if (lane == 0) wsum[wid] = sum;
    __syncthreads();

    const int n = cnt;
    if (wid == 0) {
        float s8 = (lane < 8) ? wsum[lane] : 0.f;
#pragma unroll
        for (int offs = 4; offs; offs >>= 1) s8 += __shfl_xor_sync(0xffffffffu, s8, offs);
        if (lane == 0) bsum = s8;

        u64 ldist = packvi(-INFINITY, 0x7ffffffe);
        if (n >= Kn && n <= CAP) {
            for (int i = 0; i < n; i++) winsert(ldist, cand[i], lane);
        } else {
            // fallback (statistically never): full scalar rescan by warp 0
            u64 t[Kn];
#pragma unroll
            for (int j = 0; j < Kn; j++) t[j] = packvi(-INFINITY, 0x7ffffffe);
            for (int q = lane; q < Vn; q += 32) {
                u64 pk = packvi(rowp[q], q);
                if (pk > t[Kn - 1]) {
                    u64 x = pk;
#pragma unroll
                    for (int j = 0; j < Kn; j++) {
                        if (x > t[j]) { u64 tmp = t[j]; t[j] = x; x = tmp; }
                    }
                }
            }
            int head = 0;
#pragma unroll
            for (int k = 0; k < Kn; k++) {
                u64 c = (head < Kn) ? t[head] : 0ull;
#pragma unroll
                for (int offs = 16; offs; offs >>= 1) {
                    u64 o = __shfl_xor_sync(0xffffffffu, c, offs);
                    if (o > c) c = o;
                }
                if (head < Kn && t[head] == c) head++;
                winsert(ldist, c, lane);
            }
        }
        if (lane < Kn) fin[lane] = ldist;
    }
    __syncthreads();

    float mk = attn[b * Sn + s + 1];
    if (tid < Kn) {
        u64 pk = fin[tid];
        float lgk = unpackv(pk);
        int id = unpacki(pk);
        float w; int oid;
        if (mk > 0.f) { w = __logf(1.f + fmaxf(lgk, 0.f)) * mk; oid = id; }
        else          { w = 0.f; oid = tid; }
        out[OFF_IDS + row * Kn + tid] = (float)oid;
        out[OFF_W   + row * Kn + tid] = w;
        if (w > 0.f) {
            atomicAdd(&out[OFF_RM + b * Vn + id], 1.f);
            atomicAdd(&g_pos, 1.f);
        }
    }
    if (tid == 0) g_rowinv[row] = 1.f / bsum;
}

// ---------------- Kernel B: per-(b,v) pass over s (8 front-batched loads) ----------------
// (R7 version: measured near the HBM roof)
__global__ __launch_bounds__(256) void cols_kernel(const float* __restrict__ logits,
                                                   const float* __restrict__ attn,
                                                   float* __restrict__ out) {
    const int tid = threadIdx.x;
    const int b = blockIdx.y;
    const int pv = blockIdx.x * 256 + tid;

    __shared__ float shi[256];
    __shared__ float shon[256];
    shi[tid]  = g_rowinv[b * 256 + tid];
    shon[tid] = attn[b * Sn + 1 + tid] > 0.f ? 0.f : -INFINITY;  // additive mask
    __syncthreads();
    if (pv >= HALFV) return;

    const float2* __restrict__ lp =
        (const float2*)(logits + ((size_t)b * Sn + 1) * Vn) + pv;
    float M0 = -INFINITY, M1 = -INFINITY;
    float a0 = 0.f, a1 = 0.f, a2 = 0.f, a3 = 0.f;
#pragma unroll 1
    for (int s = 0; s < 256; s += 8) {
        float2 l0 = __ldcs(lp + (size_t)(s + 0) * HALFV);
        float2 l1 = __ldcs(lp + (size_t)(s + 1) * HALFV);
        float2 l2 = __ldcs(lp + (size_t)(s + 2) * HALFV);
        float2 l3 = __ldcs(lp + (size_t)(s + 3) * HALFV);
        float2 l4 = __ldcs(lp + (size_t)(s + 4) * HALFV);
        float2 l5 = __ldcs(lp + (size_t)(s + 5) * HALFV);
        float2 l6 = __ldcs(lp + (size_t)(s + 6) * HALFV);
        float2 l7 = __ldcs(lp + (size_t)(s + 7) * HALFV);
        a0 += __expf(l0.x) * shi[s + 0];  a1 += __expf(l0.y) * shi[s + 0];
        a2 += __expf(l1.x) * shi[s + 1];  a3 += __expf(l1.y) * shi[s + 1];
        a0 += __expf(l2.x) * shi[s + 2];  a1 += __expf(l2.y) * shi[s + 2];
        a2 += __expf(l3.x) * shi[s + 3];  a3 += __expf(l3.y) * shi[s + 3];
        a0 += __expf(l4.x) * shi[s + 4];  a1 += __expf(l4.y) * shi[s + 4];
        a2 += __expf(l5.x) * shi[s + 5];  a3 += __expf(l5.y) * shi[s + 5];
        a0 += __expf(l6.x) * shi[s + 6];  a1 += __expf(l6.y) * shi[s + 6];
        a2 += __expf(l7.x) * shi[s + 7];  a3 += __expf(l7.y) * shi[s + 7];
        M0 = fmaxf(M0, l0.x + shon[s + 0]);  M1 = fmaxf(M1, l0.y + shon[s + 0]);
        M0 = fmaxf(M0, l1.x + shon[s + 1]);  M1 = fmaxf(M1, l1.y + shon[s + 1]);
        M0 = fmaxf(M0, l2.x + shon[s + 2]);  M1 = fmaxf(M1, l2.y + shon[s + 2]);
        M0 = fmaxf(M0, l3.x + shon[s + 3]);  M1 = fmaxf(M1, l3.y + shon[s + 3]);
        M0 = fmaxf(M0, l4.x + shon[s + 4]);  M1 = fmaxf(M1, l4.y + shon[s + 4]);
        M0 = fmaxf(M0, l5.x + shon[s + 5]);  M1 = fmaxf(M1, l5.y + shon[s + 5]);
        M0 = fmaxf(M0, l6.x + shon[s + 6]);  M1 = fmaxf(M1, l6.y + shon[s + 6]);
        M0 = fmaxf(M0, l7.x + shon[s + 7]);  M1 = fmaxf(M1, l7.y + shon[s + 7]);
    }
    int v = 2 * pv;
    out[OFF_RR + b * Vn + v]     = __logf(1.f + fmaxf(M0, 0.f));
    out[OFF_RR + b * Vn + v + 1] = __logf(1.f + fmaxf(M1, 0.f));
    out[OFF_SS + b * Vn + v]     = (a0 + a2);
    out[OFF_SS + b * Vn + v + 1] = (a1 + a3);
}

// ---------------- Kernel C: expert_repr, lane-coalesced W through L1 ----------------
#define EK_ROWS 4
__global__ __launch_bounds__(256) void expert_kernel(const float* __restrict__ hidden,
                                                     const float* __restrict__ attn,
                                                     const float* __restrict__ W,
                                                     const float* __restrict__ bt,
                                                     float* __restrict__ out) {
    __shared__ float hrow[Hn];
    const int tid = threadIdx.x;
    const int lane = tid & 31;
    const int wid = tid >> 5;
    const int p0 = wid * 4;

    const float* __restrict__ w0 = W + (p0 + 0) * Hn + lane;
    const float* __restrict__ w1 = W + (p0 + 1) * Hn + lane;
    const float* __restrict__ w2 = W + (p0 + 2) * Hn + lane;
    const float* __restrict__ w3 = W + (p0 + 3) * Hn + lane;

    for (int r = 0; r < EK_ROWS; r++) {
        const int row = blockIdx.x * EK_ROWS + r;
        const int b = row >> 8;
        const int s = row & 255;
        const size_t hbase = ((size_t)b * Sn + s + 1) * Hn;
#pragma unroll
        for (int c = 0; c < 3; c++) hrow[c * 256 + tid] = hidden[hbase + c * 256 + tid];
        __syncthreads();

        float a0 = 0.f, a1 = 0.f, a2 = 0.f, a3 = 0.f;
#pragma unroll
        for (int k = 0; k < Hn / 32; k++) {
            float hv = hrow[k * 32 + lane];
            a0 += hv * __ldg(w0 + k * 32);
            a1 += hv * __ldg(w1 + k * 32);
            a2 += hv * __ldg(w2 + k * 32);
            a3 += hv * __ldg(w3 + k * 32);
        }
#pragma unroll
        for (int off = 16; off; off >>= 1) {
            a0 += __shfl_xor_sync(0xffffffffu, a0, off);
            a1 += __shfl_xor_sync(0xffffffffu, a1, off);
            a2 += __shfl_xor_sync(0xffffffffu, a2, off);
            a3 += __shfl_xor_sync(0xffffffffu, a3, off);
        }
        if (lane == 0) {
            float mk = attn[b * Sn + s + 1];
            if (wid == 0) out[OFF_MASK + row] = mk;
            out[OFF_ER + row * Pn + p0 + 0] = (a0 + bt[p0 + 0]) * mk;
            out[OFF_ER + row * Pn + p0 + 1] = (a1 + bt[p0 + 1]) * mk;
            out[OFF_ER + row * Pn + p0 + 2] = (a2 + bt[p0 + 2]) * mk;
            out[OFF_ER + row * Pn + p0 + 3] = (a3 + bt[p0 + 3]) * mk;
        }
        __syncthreads();
    }
}

// ---------------- Kernel D: avg_cond / avg_marg ----------------
__global__ __launch_bounds__(256) void finalize_kernel(float* __restrict__ out) {
    const int tid = threadIdx.x;
    int v = blockIdx.x * 256 + tid;
    float mx = 0.f;
    if (v < Vn) {
#pragma unroll
        for (int b = 0; b < Bn; b++) mx = fmaxf(mx, out[OFF_RM + b * Vn + v]);
    }
    __shared__ float red[256];
    red[tid] = mx; __syncthreads();
    for (int off = 128; off > 0; off >>= 1) {
        if (tid < off) red[tid] += red[tid + off];
        __syncthreads();
    }
    if (tid == 0) atomicAdd(&out[OFF_MARG], red[0]);
    if (blockIdx.x == 0 && tid == 0) out[OFF_COND] = g_pos * (1.f / Bn);
}

extern "C" void kernel_launch(void* const* d_in, const int* in_sizes, int n_in,
                              void* d_out, int out_size) {
    const float *hidden = nullptr, *logits = nullptr, *attn = nullptr, *W = nullptr, *bt = nullptr;
    for (int i = 0; i < n_in; i++) {
        long n = in_sizes[i];
        if      (n == (long)Bn * Sn * Vn) logits = (const float*)d_in[i];
        else if (n == (long)Bn * Sn * Hn) hidden = (const float*)d_in[i];
        else if (n == (long)Bn * Sn)      attn   = (const float*)d_in[i];
        else if (n == (long)Pn * Hn)      W      = (const float*)d_in[i];
        else if (n == (long)Pn)           bt     = (const float*)d_in[i];
    }
    float* out = (float*)d_out;

    static int configured = 0;
    if (!configured) {
        cudaFuncSetAttribute(rows_kernel, cudaFuncAttributeMaxDynamicSharedMemorySize,
                             ROWS_DSMEM);
        configured = 1;
    }

    zero_kernel<<<(OFF_SS + 255) / 256, 256>>>(out);                       // 1
    expert_kernel<<<NROWS / EK_ROWS, 256>>>(hidden, attn, W, bt, out);     // 2
    spacer_kernel<<<1, 32>>>();                                            // 3
    rows_kernel<<<NROWS, 256, ROWS_DSMEM>>>(logits, attn, out);            // 4 (profiled)
    cols_kernel<<<dim3((HALFV + 255) / 256, Bn), 256>>>(logits, attn, out);// 5
    finalize_kernel<<<(Vn + 255) / 256, 256>>>(out);                       // 6
}

// round 12
// speedup vs baseline: 1.0503x; 1.0503x over previous
#include <cuda_runtime.h>
#include <math.h>

#define Bn 16
#define Sn 257
#define Hn 768
#define Vn 30522
#define Pn 32
#define Kn 8
#define NROWS (Bn * 256)
#define HALFV (Vn / 2)   // 15261 float2 per row
#define N4    7630       // float4 count in the aligned body of a row
#define CAP 512          // candidate buffer (expected ~41 used)

#define TILE4   1024     // float4 per tile (16KB)  -- R9 best config
#define NTILES  8
#define STAGES  3
#define ROWS_DSMEM (STAGES * TILE4 * 16)   // 48KB

// Output layout (flat f32, reference tuple order)
#define OFF_COND 0
#define OFF_MARG 1
#define OFF_RM   2
#define OFF_SS   (OFF_RM + Bn * Vn)
#define OFF_MASK (OFF_SS + Bn * Vn)
#define OFF_RR   (OFF_MASK + Bn * 256)
#define OFF_IDS  (OFF_RR + Bn * Vn)
#define OFF_ER   (OFF_IDS + NROWS * Kn)
#define OFF_W    (OFF_ER + NROWS * Pn)

__device__ float g_rowinv[NROWS];
__device__ float g_pos;

typedef unsigned long long u64;
typedef unsigned int u32;

// spacer (position 2) so cols lands in the ncu capture window (pos 4)
__global__ void spacer_kernel() {}

// ---- monotone (value,index) packing: larger value first, ties -> smaller idx ----
__device__ __forceinline__ u64 packvi(float f, int idx) {
    u32 u = __float_as_uint(f);
    u = (u & 0x80000000u) ? ~u : (u | 0x80000000u);
    return ((u64)u << 32) | (u32)(0xFFFFFFFFu - (u32)idx);
}
__device__ __forceinline__ float unpackv(u64 p) {
    u32 k = (u32)(p >> 32);
    u32 u = (k & 0x80000000u) ? (k & 0x7FFFFFFFu) : ~k;
    return __uint_as_float(u);
}
__device__ __forceinline__ int unpacki(u64 p) {
    return (int)(0xFFFFFFFFu - (u32)p);
}

// Warp-distributed sorted top-8 insert: lanes 0..7 hold the list (lane0 =
// largest). pk must be warp-uniform.
__device__ __forceinline__ void winsert(u64& ldist, u64 pk, int lane) {
    u64 up = __shfl_up_sync(0xffffffffu, ldist, 1);
    if (lane == 0) up = ~0ull;                       // +inf sentinel
    ldist = (ldist >= pk) ? ldist : ((up >= pk) ? pk : up);
}

__device__ __forceinline__ void cpa16(float4* dst_smem, const float4* src) {
    u32 d = (u32)__cvta_generic_to_shared(dst_smem);
    asm volatile("cp.async.cg.shared.global [%0], [%1], 16;" :: "r"(d), "l"(src));
}
__device__ __forceinline__ void cpa_commit() {
    asm volatile("cp.async.commit_group;");
}
__device__ __forceinline__ void cpa_wait2() {
    asm volatile("cp.async.wait_group 2;");
}

// ---------------- Kernel A: per-(b,s) row pass over V (exact R9 config) ----------------
// sumexp (no max subtraction: logits O(1), exp(lg)/sum == ref softmax) +
// threshold-gathered top-8 (fallback rescan keeps correctness for ANY input).
// cp.async 3-stage smem pipeline, 16KB tiles (measured best: 99.6us, DRAM 64%).
__global__ __launch_bounds__(256) void rows_kernel(const float* __restrict__ logits,
                                                   const float* __restrict__ attn,
                                                   float* __restrict__ out) {
    extern __shared__ float4 stage[];   // [STAGES * TILE4]
    const int row = blockIdx.x;
    const int b = row >> 8;
    const int s = row & 255;
    const int tid = threadIdx.x;
    const int lane = tid & 31;
    const int wid = tid >> 5;

    const size_t fbase = ((size_t)b * Sn + (s + 1)) * Vn;   // float index of row start
    const float* __restrict__ rowp = logits + fbase;
    const int off = (int)(fbase & 3);                        // 0 or 2
    const float4* __restrict__ lp4 = (const float4*)(rowp + off);
    const int e0 = (off == 2) ? 0 : (Vn - 2);                // the 2 peeled elements

    __shared__ int   cnt;
    __shared__ u64   cand[CAP];
    __shared__ float wsum[8];
    __shared__ u64   fin[Kn];
    __shared__ float bsum;
    if (tid == 0) cnt = 0;
    __syncthreads();

    const float T = 3.0f;
    float sum0 = 0.f, sum1 = 0.f, sum2 = 0.f, sum3 = 0.f;

#define PUSH(f, ix)                                                      \
    {                                                                    \
        int _p = atomicAdd(&cnt, 1);                                     \
        if (_p < CAP) cand[_p] = packvi((f), (ix));                      \
    }
#define PROC4(v, ix0)                                                    \
    {                                                                    \
        sum0 += __expf((v).x);                                           \
        sum1 += __expf((v).y);                                           \
        sum2 += __expf((v).z);                                           \
        sum3 += __expf((v).w);                                           \
        float _mx = fmaxf(fmaxf((v).x, (v).y), fmaxf((v).z, (v).w));     \
        if (_mx >= T) {  /* rare */                                      \
            if ((v).x >= T) PUSH((v).x, (ix0));                          \
            if ((v).y >= T) PUSH((v).y, (ix0) + 1);                      \
            if ((v).z >= T) PUSH((v).z, (ix0) + 2);                      \
            if ((v).w >= T) PUSH((v).w, (ix0) + 3);                      \
        }                                                                \
    }

    // peeled scalar elements (2 per row, handled by tid 0/1)
    if (tid < 2) {
        float f = rowp[e0 + tid];
        sum0 += __expf(f);
        if (f >= T) PUSH(f, e0 + tid);
    }

    // fetch tile t into slot t%STAGES (thread-private 16B cells); empty
    // commit for t >= NTILES keeps the wait_group count uniform.
#define FETCH(t)                                                              \
    {                                                                         \
        if ((t) < NTILES) {                                                   \
            int _base = (t) * TILE4;                                          \
            float4* _slot = stage + ((t) % STAGES) * TILE4;                   \
            _Pragma("unroll")                                                 \
            for (int _j = 0; _j < 4; _j++) {                                  \
                int _i = _j * 256 + tid;                                      \
                if (_base + _i < N4) cpa16(_slot + _i, lp4 + _base + _i);     \
            }                                                                 \
        }                                                                     \
        cpa_commit();                                                         \
    }

    FETCH(0); FETCH(1); FETCH(2);
#pragma unroll 1
    for (int t = 0; t < NTILES; t++) {
        cpa_wait2();                       // tile t complete (3 pending -> 2)
        const int base = t * TILE4;
        float4* slot = stage + (t % STAGES) * TILE4;
        const float4 NEG4 = make_float4(-INFINITY, -INFINITY, -INFINITY, -INFINITY);
        float4 r0 = (base + tid < N4)       ? slot[tid]       : NEG4;
        float4 r1 = (base + 256 + tid < N4) ? slot[256 + tid] : NEG4;
        float4 r2 = (base + 512 + tid < N4) ? slot[512 + tid] : NEG4;
        float4 r3 = (base + 768 + tid < N4) ? slot[768 + tid] : NEG4;
        FETCH(t + 3);                      // refill this slot (own cells only)
        PROC4(r0, off + 4 * (base + tid));
        PROC4(r1, off + 4 * (base + 256 + tid));
        PROC4(r2, off + 4 * (base + 512 + tid));
        PROC4(r3, off + 4 * (base + 768 + tid));
    }

    // ---- softmax-sum reduce ----
    float sum = (sum0 + sum1) + (sum2 + sum3);
#pragma unroll
    for (int offs = 16; offs; offs >>= 1) sum += __shfl_xor_sync(0xffffffffu, sum, offs);
    if (lane == 0) wsum[wid] = sum;
    __syncthreads();

    const int n = cnt;
    if (wid == 0) {
        float s8 = (lane < 8) ? wsum[lane] : 0.f;
#pragma unroll
        for (int offs = 4; offs; offs >>= 1) s8 += __shfl_xor_sync(0xffffffffu, s8, offs);
        if (lane == 0) bsum = s8;

        u64 ldist = packvi(-INFINITY, 0x7ffffffe);
        if (n >= Kn && n <= CAP) {
            for (int i = 0; i < n; i++) winsert(ldist, cand[i], lane);
        } else {
            // fallback (statistically never): full scalar rescan by warp 0
            u64 t[Kn];
#pragma unroll
            for (int j = 0; j < Kn; j++) t[j] = packvi(-INFINITY, 0x7ffffffe);
            for (int q = lane; q < Vn; q += 32) {
                u64 pk = packvi(rowp[q], q);
                if (pk > t[Kn - 1]) {
                    u64 x = pk;
#pragma unroll
                    for (int j = 0; j < Kn; j++) {
                        if (x > t[j]) { u64 tmp = t[j]; t[j] = x; x = tmp; }
                    }
                }
            }
            int head = 0;
#pragma unroll
            for (int k = 0; k < Kn; k++) {
                u64 c = (head < Kn) ? t[head] : 0ull;
#pragma unroll
                for (int offs = 16; offs; offs >>= 1) {
                    u64 o = __shfl_xor_sync(0xffffffffu, c, offs);
                    if (o > c) c = o;
                }
                if (head < Kn && t[head] == c) head++;
                winsert(ldist, c, lane);
            }
        }
        if (lane < Kn) fin[lane] = ldist;
    }
    __syncthreads();

    float mk = attn[b * Sn + s + 1];
    if (tid < Kn) {
        u64 pk = fin[tid];
        float lgk = unpackv(pk);
        int id = unpacki(pk);
        float w; int oid;
        if (mk > 0.f) { w = __logf(1.f + fmaxf(lgk, 0.f)) * mk; oid = id; }
        else          { w = 0.f; oid = tid; }
        out[OFF_IDS + row * Kn + tid] = (float)oid;
        out[OFF_W   + row * Kn + tid] = w;
        if (w > 0.f) {
            atomicAdd(&out[OFF_RM + b * Vn + id], 1.f);
            atomicAdd(&g_pos, 1.f);
        }
    }
    if (tid == 0) g_rowinv[row] = 1.f / bsum;
}

// ---------------- Kernel B: cols + fused finalize ----------------
// Runs after rows: RM region and g_pos are complete, so the avg_marg /
// avg_cond reduction is folded into the prologue (per-warp reduce + atomic).
__global__ __launch_bounds__(256) void cols_fin_kernel(const float* __restrict__ logits,
                                                       const float* __restrict__ attn,
                                                       float* __restrict__ out) {
    const int tid = threadIdx.x;
    const int b = blockIdx.y;
    const int pv = blockIdx.x * 256 + tid;
    const int lane = tid & 31;

    __shared__ float shi[256];
    __shared__ float shon[256];
    shi[tid]  = g_rowinv[b * 256 + tid];
    shon[tid] = attn[b * Sn + 1 + tid] > 0.f ? 0.f : -INFINITY;  // additive mask

    // fused finalize (only the b==0 plane of blocks; covers all v)
    if (b == 0) {
        float mx = 0.f;
        if (pv < HALFV) {
            int v0 = 2 * pv;
#pragma unroll
            for (int bb = 0; bb < Bn; bb++) {
                mx += 0.f;  // keep dependency simple
                float m0 = out[OFF_RM + bb * Vn + v0];
                float m1 = (v0 + 1 < Vn) ? out[OFF_RM + bb * Vn + v0 + 1] : 0.f;
                mx = fmaxf(mx, 0.f);
                // track maxima separately then sum both columns
                // (done below with two accumulators)
            }
        }
        // redo cleanly with two accumulators
        float mxa = 0.f, mxb = 0.f;
        if (pv < HALFV) {
            int v0 = 2 * pv;
#pragma unroll
            for (int bb = 0; bb < Bn; bb++) {
                mxa = fmaxf(mxa, out[OFF_RM + bb * Vn + v0]);
                if (v0 + 1 < Vn) mxb = fmaxf(mxb, out[OFF_RM + bb * Vn + v0 + 1]);
            }
        }
        float tot = mxa + mxb;
#pragma unroll
        for (int offs = 16; offs; offs >>= 1) tot += __shfl_xor_sync(0xffffffffu, tot, offs);
        if (lane == 0 && tot != 0.f) atomicAdd(&out[OFF_MARG], tot);
        if (blockIdx.x == 0 && tid == 0) out[OFF_COND] = g_pos * (1.f / Bn);
    }

    __syncthreads();
    if (pv >= HALFV) return;

    const float2* __restrict__ lp =
        (const float2*)(logits + ((size_t)b * Sn + 1) * Vn) + pv;
    float M0 = -INFINITY, M1 = -INFINITY;
    float a0 = 0.f, a1 = 0.f, a2 = 0.f, a3 = 0.f;
#pragma unroll 1
    for (int s = 0; s < 256; s += 8) {
        float2 l0 = __ldcs(lp + (size_t)(s + 0) * HALFV);
        float2 l1 = __ldcs(lp + (size_t)(s + 1) * HALFV);
        float2 l2 = __ldcs(lp + (size_t)(s + 2) * HALFV);
        float2 l3 = __ldcs(lp + (size_t)(s + 3) * HALFV);
        float2 l4 = __ldcs(lp + (size_t)(s + 4) * HALFV);
        float2 l5 = __ldcs(lp + (size_t)(s + 5) * HALFV);
        float2 l6 = __ldcs(lp + (size_t)(s + 6) * HALFV);
        float2 l7 = __ldcs(lp + (size_t)(s + 7) * HALFV);
        a0 += __expf(l0.x) * shi[s + 0];  a1 += __expf(l0.y) * shi[s + 0];
        a2 += __expf(l1.x) * shi[s + 1];  a3 += __expf(l1.y) * shi[s + 1];
        a0 += __expf(l2.x) * shi[s + 2];  a1 += __expf(l2.y) * shi[s + 2];
        a2 += __expf(l3.x) * shi[s + 3];  a3 += __expf(l3.y) * shi[s + 3];
        a0 += __expf(l4.x) * shi[s + 4];  a1 += __expf(l4.y) * shi[s + 4];
        a2 += __expf(l5.x) * shi[s + 5];  a3 += __expf(l5.y) * shi[s + 5];
        a0 += __expf(l6.x) * shi[s + 6];  a1 += __expf(l6.y) * shi[s + 6];
        a2 += __expf(l7.x) * shi[s + 7];  a3 += __expf(l7.y) * shi[s + 7];
        M0 = fmaxf(M0, l0.x + shon[s + 0]);  M1 = fmaxf(M1, l0.y + shon[s + 0]);
        M0 = fmaxf(M0, l1.x + shon[s + 1]);  M1 = fmaxf(M1, l1.y + shon[s + 1]);
        M0 = fmaxf(M0, l2.x + shon[s + 2]);  M1 = fmaxf(M1, l2.y + shon[s + 2]);
        M0 = fmaxf(M0, l3.x + shon[s + 3]);  M1 = fmaxf(M1, l3.y + shon[s + 3]);
        M0 = fmaxf(M0, l4.x + shon[s + 4]);  M1 = fmaxf(M1, l4.y + shon[s + 4]);
        M0 = fmaxf(M0, l5.x + shon[s + 5]);  M1 = fmaxf(M1, l5.y + shon[s + 5]);
        M0 = fmaxf(M0, l6.x + shon[s + 6]);  M1 = fmaxf(M1, l6.y + shon[s + 6]);
        M0 = fmaxf(M0, l7.x + shon[s + 7]);  M1 = fmaxf(M1, l7.y + shon[s + 7]);
    }
    int v = 2 * pv;
    out[OFF_RR + b * Vn + v]     = __logf(1.f + fmaxf(M0, 0.f));
    out[OFF_RR + b * Vn + v + 1] = __logf(1.f + fmaxf(M1, 0.f));
    out[OFF_SS + b * Vn + v]     = (a0 + a2);
    out[OFF_SS + b * Vn + v + 1] = (a1 + a3);
}

// ---------------- Kernel C: expert_repr + fused output zeroing ----------------
// Zeroes the COND/MARG/RM region (disjoint from expert's own outputs; rows,
// the only consumer, launches afterwards).
#define EK_ROWS 4
__global__ __launch_bounds__(256) void expert_kernel(const float* __restrict__ hidden,
                                                     const float* __restrict__ attn,
                                                     const float* __restrict__ W,
                                                     const float* __restrict__ bt,
                                                     float* __restrict__ out) {
    // fused zero: 262144 threads x 2 elements cover OFF_SS (488354)
    {
        int g = blockIdx.x * 256 + threadIdx.x;
        if (g < OFF_SS) out[g] = 0.f;
        int g2 = g + (NROWS / EK_ROWS) * 256;
        if (g2 < OFF_SS) out[g2] = 0.f;
        if (g == 0) g_pos = 0.f;
    }

    __shared__ float hrow[Hn];
    const int tid = threadIdx.x;
    const int lane = tid & 31;
    const int wid = tid >> 5;
    const int p0 = wid * 4;

    const float* __restrict__ w0 = W + (p0 + 0) * Hn + lane;
    const float* __restrict__ w1 = W + (p0 + 1) * Hn + lane;
    const float* __restrict__ w2 = W + (p0 + 2) * Hn + lane;
    const float* __restrict__ w3 = W + (p0 + 3) * Hn + lane;

    for (int r = 0; r < EK_ROWS; r++) {
        const int row = blockIdx.x * EK_ROWS + r;
        const int b = row >> 8;
        const int s = row & 255;
        const size_t hbase = ((size_t)b * Sn + s + 1) * Hn;
#pragma unroll
        for (int c = 0; c < 3; c++) hrow[c * 256 + tid] = hidden[hbase + c * 256 + tid];
        __syncthreads();

        float a0 = 0.f, a1 = 0.f, a2 = 0.f, a3 = 0.f;
#pragma unroll
        for (int k = 0; k < Hn / 32; k++) {
            float hv = hrow[k * 32 + lane];
            a0 += hv * __ldg(w0 + k * 32);
            a1 += hv * __ldg(w1 + k * 32);
            a2 += hv * __ldg(w2 + k * 32);
            a3 += hv * __ldg(w3 + k * 32);
        }
#pragma unroll
        for (int off = 16; off; off >>= 1) {
            a0 += __shfl_xor_sync(0xffffffffu, a0, off);
            a1 += __shfl_xor_sync(0xffffffffu, a1, off);
            a2 += __shfl_xor_sync(0xffffffffu, a2, off);
            a3 += __shfl_xor_sync(0xffffffffu, a3, off);
        }
        if (lane == 0) {
            float mk = attn[b * Sn + s + 1];
            if (wid == 0) out[OFF_MASK + row] = mk;
            out[OFF_ER + row * Pn + p0 + 0] = (a0 + bt[p0 + 0]) * mk;
            out[OFF_ER + row * Pn + p0 + 1] = (a1 + bt[p0 + 1]) * mk;
            out[OFF_ER + row * Pn + p0 + 2] = (a2 + bt[p0 + 2]) * mk;
            out[OFF_ER + row * Pn + p0 + 3] = (a3 + bt[p0 + 3]) * mk;
        }
        __syncthreads();
    }
}

extern "C" void kernel_launch(void* const* d_in, const int* in_sizes, int n_in,
                              void* d_out, int out_size) {
    const float *hidden = nullptr, *logits = nullptr, *attn = nullptr, *W = nullptr, *bt = nullptr;
    for (int i = 0; i < n_in; i++) {
        long n = in_sizes[i];
        if      (n == (long)Bn * Sn * Vn) logits = (const float*)d_in[i];
        else if (n == (long)Bn * Sn * Hn) hidden = (const float*)d_in[i];
        else if (n == (long)Bn * Sn)      attn   = (const float*)d_in[i];
        else if (n == (long)Pn * Hn)      W      = (const float*)d_in[i];
        else if (n == (long)Pn)           bt     = (const float*)d_in[i];
    }
    float* out = (float*)d_out;

    static int configured = 0;
    if (!configured) {
        cudaFuncSetAttribute(rows_kernel, cudaFuncAttributeMaxDynamicSharedMemorySize,
                             ROWS_DSMEM);
        configured = 1;
    }

    expert_kernel<<<NROWS / EK_ROWS, 256>>>(hidden, attn, W, bt, out);      // 1 (+zero)
    spacer_kernel<<<1, 32>>>();                                             // 2
    rows_kernel<<<NROWS, 256, ROWS_DSMEM>>>(logits, attn, out);             // 3
    cols_fin_kernel<<<dim3((HALFV + 255) / 256, Bn), 256>>>(logits, attn, out); // 4 (profiled, +finalize)
}